// round 1
// baseline (speedup 1.0000x reference)
#include <cuda_runtime.h>
#include <cuda_bf16.h>

#define N_NODES 8192
#define NFEAT   256
#define NHID    64
#define NHEADS  4
#define NCLASS  121
#define MAXDEG  256
#define ALPHA_LRELU 0.2f

// ---------------- scratch (static device globals; no allocation) ----------------
__device__ int   g_deg[N_NODES];
__device__ int   g_nbr[N_NODES * MAXDEG];
__device__ float g_Wh [N_NODES * 256];        // layer-1 Wh, all 4 heads concatenated
__device__ float g_fsrc[NHEADS * N_NODES];
__device__ float g_fdst[NHEADS * N_NODES];
__device__ float g_hcat[N_NODES * 256];
__device__ float g_Wh2[N_NODES * 128];        // layer-2 Wh, padded to 128 cols
__device__ float g_f2src[N_NODES];
__device__ float g_f2dst[N_NODES];

// ---------------- CSR build: warp per row, ballot compaction (deterministic) ----
__global__ __launch_bounds__(256) void build_csr(const float* __restrict__ adj) {
    int warp = (blockIdx.x * blockDim.x + threadIdx.x) >> 5;
    int lane = threadIdx.x & 31;
    if (warp >= N_NODES) return;
    const float4* row = reinterpret_cast<const float4*>(adj + (size_t)warp * N_NODES);
    int cnt = 0;
    int* out = g_nbr + warp * MAXDEG;
    for (int base = 0; base < N_NODES / 4; base += 32) {
        float4 v = row[base + lane];
        float vv[4] = {v.x, v.y, v.z, v.w};
        int col0 = (base + lane) * 4;
        #pragma unroll
        for (int q = 0; q < 4; q++) {
            unsigned m = __ballot_sync(0xffffffffu, vv[q] > 0.0f);
            if (vv[q] > 0.0f) {
                int pos = cnt + __popc(m & ((1u << lane) - 1u));
                if (pos < MAXDEG) out[pos] = col0 + q;
            }
            cnt += __popc(m);
        }
    }
    if (lane == 0) g_deg[warp] = cnt < MAXDEG ? cnt : MAXDEG;
}

// ---------------- tiled fp32 GEMM: BM=64, BN=64, BK=16, 256 thr, 4x4 microtile --
// MODE 0: B(k,c) = Ws[(c>>6)*NFEAT*NHID + k*NHID + (c&63)]   (head-fused layer 1)
// MODE 1: B(k,c) = (c<NCLASS) ? W_out[k*NCLASS + c] : 0      (layer 2)
template <int MODE>
__global__ __launch_bounds__(256) void sgemm(const float* __restrict__ A,
                                             const float* __restrict__ B,
                                             float* __restrict__ C, int ldc) {
    __shared__ float sA[16][64];
    __shared__ float sB[16][68];   // +4 pad to dodge conflicts

    int tid = threadIdx.x;
    int m0 = blockIdx.y * 64;
    int c0 = blockIdx.x * 64;

    int a_row  = tid >> 2;            // 0..63
    int a_col4 = (tid & 3) * 4;       // 0,4,8,12
    int b_k    = tid >> 4;            // 0..15
    int b_c4   = (tid & 15) * 4;      // 0..60

    int ty = tid >> 4;                // 0..15
    int tx = tid & 15;                // 0..15

    float acc[4][4];
    #pragma unroll
    for (int i = 0; i < 4; i++)
        #pragma unroll
        for (int j = 0; j < 4; j++) acc[i][j] = 0.0f;

    for (int k0 = 0; k0 < NFEAT; k0 += 16) {
        // load A tile (transposed into sA[k][m])
        float4 av = *reinterpret_cast<const float4*>(A + (size_t)(m0 + a_row) * NFEAT + k0 + a_col4);
        sA[a_col4 + 0][a_row] = av.x;
        sA[a_col4 + 1][a_row] = av.y;
        sA[a_col4 + 2][a_row] = av.z;
        sA[a_col4 + 3][a_row] = av.w;
        // load B tile
        if (MODE == 0) {
            // head fixed per block: c0 multiple of 64
            const float* bp = B + (size_t)(c0 >> 6) * (NFEAT * NHID) + (size_t)(k0 + b_k) * NHID + b_c4;
            float4 bv = *reinterpret_cast<const float4*>(bp);
            sB[b_k][b_c4 + 0] = bv.x;
            sB[b_k][b_c4 + 1] = bv.y;
            sB[b_k][b_c4 + 2] = bv.z;
            sB[b_k][b_c4 + 3] = bv.w;
        } else {
            #pragma unroll
            for (int j = 0; j < 4; j++) {
                int c = c0 + b_c4 + j;
                sB[b_k][b_c4 + j] = (c < NCLASS) ? B[(size_t)(k0 + b_k) * NCLASS + c] : 0.0f;
            }
        }
        __syncthreads();

        #pragma unroll
        for (int kk = 0; kk < 16; kk++) {
            float a[4], b[4];
            #pragma unroll
            for (int i = 0; i < 4; i++) a[i] = sA[kk][ty * 4 + i];
            #pragma unroll
            for (int j = 0; j < 4; j++) b[j] = sB[kk][tx * 4 + j];
            #pragma unroll
            for (int i = 0; i < 4; i++)
                #pragma unroll
                for (int j = 0; j < 4; j++) acc[i][j] = fmaf(a[i], b[j], acc[i][j]);
        }
        __syncthreads();
    }

    #pragma unroll
    for (int i = 0; i < 4; i++) {
        float* cp = C + (size_t)(m0 + ty * 4 + i) * ldc + c0 + tx * 4;
        #pragma unroll
        for (int j = 0; j < 4; j++) cp[j] = acc[i][j];
    }
}

// ---------------- per-(node,head) src/dst scores, layer 1 ----------------------
__global__ __launch_bounds__(256) void compute_f1(const float* __restrict__ a_heads) {
    int gw   = (blockIdx.x * blockDim.x + threadIdx.x) >> 5;  // 0..32767
    int lane = threadIdx.x & 31;
    int i = gw >> 2, h = gw & 3;
    const float* wh = g_Wh + (size_t)i * 256 + h * 64;
    const float* a  = a_heads + h * (2 * NHID);
    float s1 = fmaf(wh[lane], a[lane], wh[lane + 32] * a[lane + 32]);
    float s2 = fmaf(wh[lane], a[64 + lane], wh[lane + 32] * a[64 + lane + 32]);
    #pragma unroll
    for (int o = 16; o; o >>= 1) {
        s1 += __shfl_xor_sync(0xffffffffu, s1, o);
        s2 += __shfl_xor_sync(0xffffffffu, s2, o);
    }
    if (lane == 0) { g_fsrc[h * N_NODES + i] = s1; g_fdst[h * N_NODES + i] = s2; }
}

// ---------------- layer-1 sparse attention + aggregate + ELU -------------------
__global__ __launch_bounds__(256) void layer1_agg() {
    __shared__ int   s_nbr[MAXDEG];
    __shared__ float s_w[NHEADS][MAXDEG];
    __shared__ float s_red[NHEADS][2];

    int i   = blockIdx.x;
    int tid = threadIdx.x;
    int deg = g_deg[i];

    for (int t = tid; t < deg; t += 256) s_nbr[t] = g_nbr[i * MAXDEG + t];
    __syncthreads();

    int h   = tid >> 6;
    int t64 = tid & 63;
    int sub = (tid >> 5) & 1;

    float fsrc = g_fsrc[h * N_NODES + i];
    const float* fd = g_fdst + h * N_NODES;

    float lmax = -1e30f;
    for (int j = t64; j < deg; j += 64) {
        float e = fsrc + fd[s_nbr[j]];
        e = e >= 0.0f ? e : ALPHA_LRELU * e;
        s_w[h][j] = e;
        lmax = fmaxf(lmax, e);
    }
    #pragma unroll
    for (int o = 16; o; o >>= 1) lmax = fmaxf(lmax, __shfl_xor_sync(0xffffffffu, lmax, o));
    if ((tid & 31) == 0) s_red[h][sub] = lmax;
    __syncthreads();
    float m = fmaxf(s_red[h][0], s_red[h][1]);

    float lsum = 0.0f;
    for (int j = t64; j < deg; j += 64) {
        float w = __expf(s_w[h][j] - m);
        s_w[h][j] = w;
        lsum += w;
    }
    #pragma unroll
    for (int o = 16; o; o >>= 1) lsum += __shfl_xor_sync(0xffffffffu, lsum, o);
    __syncthreads();
    if ((tid & 31) == 0) s_red[h][sub] = lsum;
    __syncthreads();
    float inv = 1.0f / (s_red[h][0] + s_red[h][1]);

    const float* whcol = g_Wh + h * 64 + t64;
    float acc0 = 0.0f, acc1 = 0.0f;
    int j = 0;
    for (; j + 1 < deg; j += 2) {
        acc0 = fmaf(s_w[h][j],     whcol[(size_t)s_nbr[j]     << 8], acc0);
        acc1 = fmaf(s_w[h][j + 1], whcol[(size_t)s_nbr[j + 1] << 8], acc1);
    }
    if (j < deg) acc0 = fmaf(s_w[h][j], whcol[(size_t)s_nbr[j] << 8], acc0);
    float acc = (acc0 + acc1) * inv;
    float v = acc > 0.0f ? acc : expm1f(acc);
    g_hcat[(size_t)i * 256 + h * 64 + t64] = v;
}

// ---------------- layer-2 src/dst scores ---------------------------------------
__global__ __launch_bounds__(256) void compute_f2(const float* __restrict__ a_out) {
    int gw   = (blockIdx.x * blockDim.x + threadIdx.x) >> 5;  // 0..8191
    int lane = threadIdx.x & 31;
    const float* wh = g_Wh2 + (size_t)gw * 128;
    float s1 = 0.0f, s2 = 0.0f;
    #pragma unroll
    for (int q = 0; q < 4; q++) {
        int c = lane + q * 32;
        if (c < NCLASS) {
            float v = wh[c];
            s1 = fmaf(v, a_out[c], s1);
            s2 = fmaf(v, a_out[NCLASS + c], s2);
        }
    }
    #pragma unroll
    for (int o = 16; o; o >>= 1) {
        s1 += __shfl_xor_sync(0xffffffffu, s1, o);
        s2 += __shfl_xor_sync(0xffffffffu, s2, o);
    }
    if (lane == 0) { g_f2src[gw] = s1; g_f2dst[gw] = s2; }
}

// ---------------- layer-2 sparse attention + aggregate (no ELU) ----------------
__global__ __launch_bounds__(128) void layer2_agg(float* __restrict__ out) {
    __shared__ int   s_nbr[MAXDEG];
    __shared__ float s_w[MAXDEG];
    __shared__ float s_red[4];

    int i   = blockIdx.x;
    int tid = threadIdx.x;
    int deg = g_deg[i];

    for (int t = tid; t < deg; t += 128) s_nbr[t] = g_nbr[i * MAXDEG + t];
    __syncthreads();

    float fsrc = g_f2src[i];
    float lmax = -1e30f;
    for (int j = tid; j < deg; j += 128) {
        float e = fsrc + g_f2dst[s_nbr[j]];
        e = e >= 0.0f ? e : ALPHA_LRELU * e;
        s_w[j] = e;
        lmax = fmaxf(lmax, e);
    }
    #pragma unroll
    for (int o = 16; o; o >>= 1) lmax = fmaxf(lmax, __shfl_xor_sync(0xffffffffu, lmax, o));
    if ((tid & 31) == 0) s_red[tid >> 5] = lmax;
    __syncthreads();
    float m = fmaxf(fmaxf(s_red[0], s_red[1]), fmaxf(s_red[2], s_red[3]));

    float lsum = 0.0f;
    for (int j = tid; j < deg; j += 128) {
        float w = __expf(s_w[j] - m);
        s_w[j] = w;
        lsum += w;
    }
    #pragma unroll
    for (int o = 16; o; o >>= 1) lsum += __shfl_xor_sync(0xffffffffu, lsum, o);
    __syncthreads();
    if ((tid & 31) == 0) s_red[tid >> 5] = lsum;
    __syncthreads();
    float inv = 1.0f / (s_red[0] + s_red[1] + s_red[2] + s_red[3]);

    if (tid < NCLASS) {
        const float* whcol = g_Wh2 + tid;
        float acc0 = 0.0f, acc1 = 0.0f;
        int j = 0;
        for (; j + 1 < deg; j += 2) {
            acc0 = fmaf(s_w[j],     whcol[(size_t)s_nbr[j]     << 7], acc0);
            acc1 = fmaf(s_w[j + 1], whcol[(size_t)s_nbr[j + 1] << 7], acc1);
        }
        if (j < deg) acc0 = fmaf(s_w[j], whcol[(size_t)s_nbr[j] << 7], acc0);
        out[(size_t)i * NCLASS + tid] = (acc0 + acc1) * inv;
    }
}

// ---------------- host launch ---------------------------------------------------
extern "C" void kernel_launch(void* const* d_in, const int* in_sizes, int n_in,
                              void* d_out, int out_size) {
    const float* x       = (const float*)d_in[0];   // [8192, 256]
    const float* adj     = (const float*)d_in[1];   // [8192, 8192]
    const float* Ws      = (const float*)d_in[2];   // [4, 256, 64]
    const float* a_heads = (const float*)d_in[3];   // [4, 128]
    const float* W_out   = (const float*)d_in[4];   // [256, 121]
    const float* a_out   = (const float*)d_in[5];   // [242]
    float* out = (float*)d_out;                     // [8192, 121]

    float *dWh, *dWh2, *dHcat;
    cudaGetSymbolAddress((void**)&dWh,   g_Wh);
    cudaGetSymbolAddress((void**)&dWh2,  g_Wh2);
    cudaGetSymbolAddress((void**)&dHcat, g_hcat);

    // 1. CSR build from dense adjacency
    build_csr<<<N_NODES / 8, 256>>>(adj);

    // 2. Layer-1 GEMM (all heads fused): Wh[8192,256] = x[8192,256] @ Wall[256,256]
    sgemm<0><<<dim3(256 / 64, N_NODES / 64), 256>>>(x, Ws, dWh, 256);

    // 3. Layer-1 attention scores
    compute_f1<<<(N_NODES * NHEADS) / 8, 256>>>(a_heads);

    // 4. Layer-1 sparse softmax-aggregate + ELU
    layer1_agg<<<N_NODES, 256>>>();

    // 5. Layer-2 GEMM: Wh2[8192,121(pad 128)] = hcat @ W_out
    sgemm<1><<<dim3(128 / 64, N_NODES / 64), 256>>>(dHcat, W_out, dWh2, 128);

    // 6. Layer-2 attention scores
    compute_f2<<<N_NODES / 8, 256>>>(a_out);

    // 7. Layer-2 sparse softmax-aggregate -> output
    layer2_agg<<<N_NODES, 128>>>(out);
}